// round 13
// baseline (speedup 1.0000x reference)
#include <cuda_runtime.h>
#include <cstdint>
#include <math_constants.h>

// Problem constants: B=2, N=131072, M=512, G=20
#define BB 2
#define NN 131072
#define MM 512
#define GG 20
#define VV 8000
#define VOXINV 2.0f

#define NTHR 256
#define BPB  148                // blocks per batch
#define NBLK (BB * BPB)         // 296 = 2 CTAs/SM, one co-resident wave
#define GROUPS 32768            // NN/4 float4-groups per batch
#define MASKW 250               // VV bits / 32
#define ACCW 40000              // BB*VV*10 floats / 4 = uint4 words

// Device scratch. g_minc seeded +inf at load, re-armed by k3 every launch.
__device__ unsigned int g_minc[BB * 3] = {
    0x7F800000u, 0x7F800000u, 0x7F800000u,
    0x7F800000u, 0x7F800000u, 0x7F800000u};
__device__ float4 g_spts[BB * MM];      // compacted sampled points (.w unused)
__device__ __align__(16) float g_acc[BB * VV * 10];  // cnt,sx..sz,xx..zz

__device__ __forceinline__ int voxel_of(float px, float py, float pz,
                                        float n0, float n1, float n2) {
    int vx = (int)floorf((px - n0) * VOXINV);
    int vy = (int)floorf((py - n1) * VOXINV);
    int vz = (int)floorf((pz - n2) * VOXINV);
    vx = min(max(vx, 0), GG - 1);
    vy = min(max(vy, 0), GG - 1);
    vz = min(max(vz, 0), GG - 1);
    return (vx * GG + vy) * GG + vz;
}

// ============================================================================
// K1: zero g_acc + compact sampled points + global min. Ends with a cheap
// fence (few plain stores in flight) + PDL trigger so k2 overlaps teardown.
// ============================================================================
__global__ void __launch_bounds__(NTHR)
k1_min(const float* __restrict__ x, const int* __restrict__ sidx) {
    const int bid = blockIdx.x, tid = threadIdx.x;
    const int b = (bid < BPB) ? 0 : 1, br = bid - b * BPB;
    const int lane = tid & 31, w = tid >> 5;
    const int t = bid * NTHR + tid;      // 0..75775
    __shared__ float s_red[8 * 3];

    // zero accumulators: 40000 uint4 over 75776 threads, single shot
    if (t < ACCW) ((uint4*)g_acc)[t] = make_uint4(0u, 0u, 0u, 0u);

    // compact sampled points (the only scattered gather in the pipeline)
    if (t < BB * MM) {
        int sb = t >> 9;
        int i = __ldg(sidx + t);
        const float* p = x + ((size_t)sb * NN + i) * 3;
        g_spts[t] = make_float4(__ldg(p), __ldg(p + 1), __ldg(p + 2), 0.0f);
    }

    // coordinate min: one float4-group (4 points) per active thread
    float m0 = CUDART_INF_F, m1 = CUDART_INF_F, m2 = CUDART_INF_F;
    {
        const float4* xb = (const float4*)(x + (size_t)b * NN * 3);
        int g = br * NTHR + tid;
        if (g < GROUPS) {
            float4 f0 = __ldg(xb + (size_t)g * 3 + 0);
            float4 f1 = __ldg(xb + (size_t)g * 3 + 1);
            float4 f2 = __ldg(xb + (size_t)g * 3 + 2);
            m0 = fminf(fminf(f0.x, f0.w), fminf(f1.z, f2.y));
            m1 = fminf(fminf(f0.y, f1.x), fminf(f1.w, f2.z));
            m2 = fminf(fminf(f0.z, f1.y), fminf(f2.x, f2.w));
        }
    }
#pragma unroll
    for (int o = 16; o > 0; o >>= 1) {
        m0 = fminf(m0, __shfl_xor_sync(0xFFFFFFFFu, m0, o));
        m1 = fminf(m1, __shfl_xor_sync(0xFFFFFFFFu, m1, o));
        m2 = fminf(m2, __shfl_xor_sync(0xFFFFFFFFu, m2, o));
    }
    if (lane == 0) { s_red[w*3+0] = m0; s_red[w*3+1] = m1; s_red[w*3+2] = m2; }
    __syncthreads();
    if (tid == 0) {
        float r0 = s_red[0], r1 = s_red[1], r2 = s_red[2];
#pragma unroll
        for (int k = 1; k < 8; k++) {
            r0 = fminf(r0, s_red[k*3+0]);
            r1 = fminf(r1, s_red[k*3+1]);
            r2 = fminf(r2, s_red[k*3+2]);
        }
        // positive floats: uint bit order == float order
        atomicMin(&g_minc[b*3+0], __float_as_uint(r0));
        atomicMin(&g_minc[b*3+1], __float_as_uint(r1));
        atomicMin(&g_minc[b*3+2], __float_as_uint(r2));
        __threadfence();   // cheap: only this block's few stores/atomics
    }
    __syncthreads();
    cudaTriggerProgrammaticLaunchCompletion();
}

// ============================================================================
// K2 (PDL secondary): prologue (x loads, mask zero) overlaps k1 tail; then
// grid-dep sync; then mark + masked scalar-RED accumulation.
// NO explicit trigger: k3 must see the REDs (implicit completion).
// ============================================================================
__global__ void __launch_bounds__(NTHR)
k2_accum(const float* __restrict__ x) {
    const int bid = blockIdx.x, tid = threadIdx.x;
    const int b = (bid < BPB) ? 0 : 1, br = bid - b * BPB;
    __shared__ unsigned int s_mask[MASKW];

    if (tid < MASKW) s_mask[tid] = 0u;

    // prologue: this thread's 4 points (independent of k1's outputs)
    const int g = br * NTHR + tid;
    const bool active = (g < GROUPS);
    float4 f0, f1, f2;
    if (active) {
        const float4* xb = (const float4*)(x + (size_t)b * NN * 3);
        f0 = __ldg(xb + (size_t)g * 3 + 0);
        f1 = __ldg(xb + (size_t)g * 3 + 1);
        f2 = __ldg(xb + (size_t)g * 3 + 2);
    }

    // wait for k1's g_minc / g_spts / zeroed g_acc
    cudaGridDependencySynchronize();

    const float n0 = __uint_as_float(g_minc[b*3+0]);
    const float n1 = __uint_as_float(g_minc[b*3+1]);
    const float n2 = __uint_as_float(g_minc[b*3+2]);

    // mark this batch's 512 sampled voxels: two points per thread
    {
        float4 p0 = g_spts[b * MM + tid];
        float4 p1 = g_spts[b * MM + tid + NTHR];
        int v0 = voxel_of(p0.x, p0.y, p0.z, n0, n1, n2);
        int v1 = voxel_of(p1.x, p1.y, p1.z, n0, n1, n2);
        atomicOr(&s_mask[v0 >> 5], 1u << (v0 & 31));
        atomicOr(&s_mask[v1 >> 5], 1u << (v1 & 31));
    }
    __syncthreads();

    // masked accumulation: one float4-group (4 points) per thread
    if (active) {
        float px[4] = {f0.x, f0.w, f1.z, f2.y};
        float py[4] = {f0.y, f1.x, f1.w, f2.z};
        float pz[4] = {f0.z, f1.y, f2.x, f2.w};
#pragma unroll
        for (int k = 0; k < 4; k++) {
            int v = voxel_of(px[k], py[k], pz[k], n0, n1, n2);
            if (s_mask[v >> 5] & (1u << (v & 31))) {
                float* a = &g_acc[(size_t)(b * VV + v) * 10];
                atomicAdd(a + 0, 1.0f);
                atomicAdd(a + 1, px[k]);
                atomicAdd(a + 2, py[k]);
                atomicAdd(a + 3, pz[k]);
                atomicAdd(a + 4, px[k] * px[k]);
                atomicAdd(a + 5, px[k] * py[k]);
                atomicAdd(a + 6, px[k] * pz[k]);
                atomicAdd(a + 7, py[k] * py[k]);
                atomicAdd(a + 8, py[k] * pz[k]);
                atomicAdd(a + 9, pz[k] * pz[k]);
            }
        }
    }
}

// ============================================================================
// K3 (PDL secondary, 4 blocks x 256 — multi-block, no single-SM LSU floor):
// gather + finalize output; re-arm g_minc for the next replay.
// ============================================================================
__global__ void __launch_bounds__(256)
k3_out(float* __restrict__ out) {
    cudaGridDependencySynchronize();               // wait for k2's REDs

    const int t = blockIdx.x * 256 + threadIdx.x;  // 0..1023
    const int b = t >> 9;
    const float n0 = __uint_as_float(g_minc[b*3+0]);
    const float n1 = __uint_as_float(g_minc[b*3+1]);
    const float n2 = __uint_as_float(g_minc[b*3+2]);

    float4 p = g_spts[t];
    int v = voxel_of(p.x, p.y, p.z, n0, n1, n2);
    const float2* a2 = (const float2*)&g_acc[(size_t)(b * VV + v) * 10];

    float2 r0 = a2[0];   // cnt, sx
    float2 r1 = a2[1];   // sy, sz
    float2 r2 = a2[2];   // xx, xy
    float2 r3 = a2[3];   // xz, yy
    float2 r4 = a2[4];   // yz, zz

    float inv = 1.0f / fmaxf(r0.x, 1.0f);
    float mx = r0.y * inv, my = r1.x * inv, mz = r1.y * inv;
    float cxx = r2.x * inv - mx * mx;
    float cxy = r2.y * inv - mx * my;
    float cxz = r3.x * inv - mx * mz;
    float cyy = r3.y * inv - my * my;
    float cyz = r4.x * inv - my * mz;
    float czz = r4.y * inv - mz * mz;

    float* o = out + (size_t)t * 12;
    o[0] = mx;  o[1] = my;  o[2] = mz;
    o[3] = cxx; o[4] = cxy; o[5] = cxz;
    o[6] = cxy; o[7] = cyy; o[8] = cyz;
    o[9] = cxz; o[10] = cyz; o[11] = czz;

    // re-arm min for the next replay (graph nodes serialize)
    if (t < BB * 3) g_minc[t] = 0x7F800000u;
}

// ---------------------------------------------------------------------------
extern "C" void kernel_launch(void* const* d_in, const int* in_sizes, int n_in,
                              void* d_out, int out_size) {
    const float* x    = (const float*)d_in[0];   // (B, N, 3) f32
    const int*   sidx = (const int*)d_in[1];     // (B, M) i32
    float*       out  = (float*)d_out;           // (B, M, 12) f32

    k1_min<<<NBLK, NTHR>>>(x, sidx);

    cudaLaunchAttribute attrs[1];
    attrs[0].id = cudaLaunchAttributeProgrammaticStreamSerialization;
    attrs[0].val.programmaticStreamSerializationAllowed = 1;

    cudaLaunchConfig_t cfg2 = {};
    cfg2.gridDim = dim3(NBLK);
    cfg2.blockDim = dim3(NTHR);
    cfg2.dynamicSmemBytes = 0;
    cfg2.stream = 0;
    cfg2.attrs = attrs;
    cfg2.numAttrs = 1;
    cudaLaunchKernelEx(&cfg2, k2_accum, x);

    cudaLaunchConfig_t cfg3 = cfg2;
    cfg3.gridDim = dim3(4);
    cfg3.blockDim = dim3(256);
    cudaLaunchKernelEx(&cfg3, k3_out, out);
}

// round 14
// speedup vs baseline: 1.0201x; 1.0201x over previous
#include <cuda_runtime.h>
#include <cstdint>
#include <math_constants.h>

// Problem constants: B=2, N=131072, M=512, G=20
#define BB 2
#define NN 131072
#define MM 512
#define GG 20
#define VV 8000
#define VOXINV 2.0f

#define NTHR 256
#define BPB  148                // blocks per batch
#define NBLK (BB * BPB)         // 296 = 2 CTAs/SM, one co-resident wave
#define GROUPS 32768            // NN/4 float4-groups per batch
#define MASKW 250               // VV bits / 32
#define ACCW 40000              // BB*VV*10 floats / 4 = uint4 words

// Device scratch. g_minc seeded +inf at load, re-armed by k3 every launch
// (graph nodes serialize -> deterministic per launch).
__device__ unsigned int g_minc[BB * 3] = {
    0x7F800000u, 0x7F800000u, 0x7F800000u,
    0x7F800000u, 0x7F800000u, 0x7F800000u};
__device__ float4 g_spts[BB * MM];      // compacted sampled points (.w unused)
__device__ __align__(16) float g_acc[BB * VV * 10];  // cnt,sx..sz,xx..zz

__device__ __forceinline__ int voxel_of(float px, float py, float pz,
                                        float n0, float n1, float n2) {
    int vx = (int)floorf((px - n0) * VOXINV);
    int vy = (int)floorf((py - n1) * VOXINV);
    int vz = (int)floorf((pz - n2) * VOXINV);
    vx = min(max(vx, 0), GG - 1);
    vy = min(max(vy, 0), GG - 1);
    vz = min(max(vz, 0), GG - 1);
    return (vx * GG + vy) * GG + vz;
}

// ============================================================================
// K1: zero g_acc (single shot) + compact sampled points + global min.
// ============================================================================
__global__ void __launch_bounds__(NTHR)
k1_min(const float* __restrict__ x, const int* __restrict__ sidx) {
    const int bid = blockIdx.x, tid = threadIdx.x;
    const int b = (bid < BPB) ? 0 : 1, br = bid - b * BPB;
    const int lane = tid & 31, w = tid >> 5;
    const int t = bid * NTHR + tid;      // 0..75775
    __shared__ float s_red[8 * 3];

    // zero accumulators: 40000 uint4 over 75776 threads, single shot
    if (t < ACCW) ((uint4*)g_acc)[t] = make_uint4(0u, 0u, 0u, 0u);

    // compact sampled points (the only scattered gather in the pipeline)
    if (t < BB * MM) {
        int sb = t >> 9;
        int i = __ldg(sidx + t);
        const float* p = x + ((size_t)sb * NN + i) * 3;
        g_spts[t] = make_float4(__ldg(p), __ldg(p + 1), __ldg(p + 2), 0.0f);
    }

    // coordinate min: one float4-group (4 points) per active thread
    float m0 = CUDART_INF_F, m1 = CUDART_INF_F, m2 = CUDART_INF_F;
    {
        const float4* xb = (const float4*)(x + (size_t)b * NN * 3);
        int g = br * NTHR + tid;
        if (g < GROUPS) {
            float4 f0 = __ldg(xb + (size_t)g * 3 + 0);
            float4 f1 = __ldg(xb + (size_t)g * 3 + 1);
            float4 f2 = __ldg(xb + (size_t)g * 3 + 2);
            m0 = fminf(fminf(f0.x, f0.w), fminf(f1.z, f2.y));
            m1 = fminf(fminf(f0.y, f1.x), fminf(f1.w, f2.z));
            m2 = fminf(fminf(f0.z, f1.y), fminf(f2.x, f2.w));
        }
    }
#pragma unroll
    for (int o = 16; o > 0; o >>= 1) {
        m0 = fminf(m0, __shfl_xor_sync(0xFFFFFFFFu, m0, o));
        m1 = fminf(m1, __shfl_xor_sync(0xFFFFFFFFu, m1, o));
        m2 = fminf(m2, __shfl_xor_sync(0xFFFFFFFFu, m2, o));
    }
    if (lane == 0) { s_red[w*3+0] = m0; s_red[w*3+1] = m1; s_red[w*3+2] = m2; }
    __syncthreads();
    if (tid == 0) {
        float r0 = s_red[0], r1 = s_red[1], r2 = s_red[2];
#pragma unroll
        for (int k = 1; k < 8; k++) {
            r0 = fminf(r0, s_red[k*3+0]);
            r1 = fminf(r1, s_red[k*3+1]);
            r2 = fminf(r2, s_red[k*3+2]);
        }
        // positive floats: uint bit order == float order
        atomicMin(&g_minc[b*3+0], __float_as_uint(r0));
        atomicMin(&g_minc[b*3+1], __float_as_uint(r1));
        atomicMin(&g_minc[b*3+2], __float_as_uint(r2));
    }
}

// ============================================================================
// K2: smem mark (2 sampled points/thread) + masked scalar-RED accumulation
// (exactly one float4-group per thread, loads issued after the mark phase
// to keep the f0-f2 live range short).
// ============================================================================
__global__ void __launch_bounds__(NTHR)
k2_accum(const float* __restrict__ x) {
    const int bid = blockIdx.x, tid = threadIdx.x;
    const int b = (bid < BPB) ? 0 : 1, br = bid - b * BPB;
    __shared__ unsigned int s_mask[MASKW];

    if (tid < MASKW) s_mask[tid] = 0u;
    const float n0 = __uint_as_float(g_minc[b*3+0]);
    const float n1 = __uint_as_float(g_minc[b*3+1]);
    const float n2 = __uint_as_float(g_minc[b*3+2]);
    __syncthreads();

    // mark this batch's 512 sampled voxels: two points per thread
    {
        float4 p0 = g_spts[b * MM + tid];
        float4 p1 = g_spts[b * MM + tid + NTHR];
        int v0 = voxel_of(p0.x, p0.y, p0.z, n0, n1, n2);
        int v1 = voxel_of(p1.x, p1.y, p1.z, n0, n1, n2);
        atomicOr(&s_mask[v0 >> 5], 1u << (v0 & 31));
        atomicOr(&s_mask[v1 >> 5], 1u << (v1 & 31));
    }
    __syncthreads();

    // masked accumulation: one float4-group (4 points) per thread
    const int g = br * NTHR + tid;
    if (g < GROUPS) {
        const float4* xb = (const float4*)(x + (size_t)b * NN * 3);
        float4 f0 = __ldg(xb + (size_t)g * 3 + 0);
        float4 f1 = __ldg(xb + (size_t)g * 3 + 1);
        float4 f2 = __ldg(xb + (size_t)g * 3 + 2);
        float px[4] = {f0.x, f0.w, f1.z, f2.y};
        float py[4] = {f0.y, f1.x, f1.w, f2.z};
        float pz[4] = {f0.z, f1.y, f2.x, f2.w};
#pragma unroll
        for (int k = 0; k < 4; k++) {
            int v = voxel_of(px[k], py[k], pz[k], n0, n1, n2);
            if (s_mask[v >> 5] & (1u << (v & 31))) {
                float* a = &g_acc[(size_t)(b * VV + v) * 10];
                atomicAdd(a + 0, 1.0f);
                atomicAdd(a + 1, px[k]);
                atomicAdd(a + 2, py[k]);
                atomicAdd(a + 3, pz[k]);
                atomicAdd(a + 4, px[k] * px[k]);
                atomicAdd(a + 5, px[k] * py[k]);
                atomicAdd(a + 6, px[k] * pz[k]);
                atomicAdd(a + 7, py[k] * py[k]);
                atomicAdd(a + 8, py[k] * pz[k]);
                atomicAdd(a + 9, pz[k] * pz[k]);
            }
        }
    }
}

// ============================================================================
// K3: gather + finalize output (B, M, 12); re-arm g_minc for next launch.
// grid = 4 x 256 (multi-block: avoids the single-SM LSU dispatch floor);
// float2 record loads (records are 40B, 8B-aligned).
// ============================================================================
__global__ void __launch_bounds__(256)
k3_out(float* __restrict__ out) {
    const int t = blockIdx.x * 256 + threadIdx.x;   // 0..1023
    const int b = t >> 9;
    const float n0 = __uint_as_float(g_minc[b*3+0]);
    const float n1 = __uint_as_float(g_minc[b*3+1]);
    const float n2 = __uint_as_float(g_minc[b*3+2]);

    float4 p = g_spts[t];
    int v = voxel_of(p.x, p.y, p.z, n0, n1, n2);
    const float2* a2 = (const float2*)&g_acc[(size_t)(b * VV + v) * 10];

    float2 r0 = a2[0];   // cnt, sx
    float2 r1 = a2[1];   // sy, sz
    float2 r2 = a2[2];   // xx, xy
    float2 r3 = a2[3];   // xz, yy
    float2 r4 = a2[4];   // yz, zz

    float inv = 1.0f / fmaxf(r0.x, 1.0f);
    float mx = r0.y * inv, my = r1.x * inv, mz = r1.y * inv;
    float cxx = r2.x * inv - mx * mx;
    float cxy = r2.y * inv - mx * my;
    float cxz = r3.x * inv - mx * mz;
    float cyy = r3.y * inv - my * my;
    float cyz = r4.x * inv - my * mz;
    float czz = r4.y * inv - mz * mz;

    float* o = out + (size_t)t * 12;
    o[0] = mx;  o[1] = my;  o[2] = mz;
    o[3] = cxx; o[4] = cxy; o[5] = cxz;
    o[6] = cxy; o[7] = cyy; o[8] = cyz;
    o[9] = cxz; o[10] = cyz; o[11] = czz;

    // re-arm min for the next replay (graph nodes serialize)
    if (t < BB * 3) g_minc[t] = 0x7F800000u;
}

// ---------------------------------------------------------------------------
extern "C" void kernel_launch(void* const* d_in, const int* in_sizes, int n_in,
                              void* d_out, int out_size) {
    const float* x    = (const float*)d_in[0];   // (B, N, 3) f32
    const int*   sidx = (const int*)d_in[1];     // (B, M) i32
    float*       out  = (float*)d_out;           // (B, M, 12) f32

    k1_min<<<NBLK, NTHR>>>(x, sidx);
    k2_accum<<<NBLK, NTHR>>>(x);
    k3_out<<<4, 256>>>(out);
}